// round 10
// baseline (speedup 1.0000x reference)
#include <cuda_runtime.h>
#include <cuda_bf16.h>
#include <math.h>

// ---------------------------------------------------------------------------
// ELMo embeddings, fp32 with packed f32x2 FMA (Blackwell dual-FP32 path).
// ---------------------------------------------------------------------------

namespace {
constexpr int Bn = 8;     // batch
constexpr int Tn = 96;    // time
constexpr int En = 256;   // embed dim
constexpr int Hn = 2048;  // hidden
constexpr int Pn = 256;   // projection
constexpr int Gn = 8192;  // 4*H
constexpr int NBLK = 128; // persistent grid (2 dirs x 64)
constexpr int DBLK = 64;  // blocks per direction
}

// scratch (device globals; allocation-free)
__device__ float g_emb[Bn * Tn * En];
__device__ float g_y0[2][Bn * Tn * Pn];
__device__ float g_y1[2][Bn * Tn * Pn];
__device__ float g_xW[2][(size_t)Tn * Bn * Gn];  // x@Wk+b, step-major
__device__ float g_h[2][Bn * Pn];
__device__ float g_a[2][Bn * Hn];
__device__ float g_mean[3][Bn];
__device__ float g_var[3][Bn];

// per-direction barrier state (monotonic; never reset -> graph-replay safe)
__device__ unsigned g_cnt[2];
__device__ unsigned g_flag[2];

// ---- packed f32x2 helpers --------------------------------------------------
__device__ __forceinline__ unsigned long long pack2(float x, float y) {
    unsigned long long r;
    asm("mov.b64 %0, {%1, %2};" : "=l"(r) : "f"(x), "f"(y));
    return r;
}
__device__ __forceinline__ void ffma2(unsigned long long& acc,
                                      unsigned long long a, unsigned long long b) {
    asm("fma.rn.f32x2 %0, %1, %2, %0;" : "+l"(acc) : "l"(a), "l"(b));
}
__device__ __forceinline__ float2 unpack2(unsigned long long v) {
    float x, y;
    asm("mov.b64 {%0, %1}, %2;" : "=f"(x), "=f"(y) : "l"(v));
    return make_float2(x, y);
}

// ---------------------------------------------------------------------------
__global__ void k_embed(const int* __restrict__ tok, const float* __restrict__ tab) {
    int i = blockIdx.x * 256 + threadIdx.x;  // B*T*E = 196608
    int bt = i >> 8;
    int e = i & 255;
    g_emb[i] = tab[(size_t)tok[bt] * En + e];
}

// ---------------------------------------------------------------------------
// xW GEMM: M=768 (s,b), N=8192, K=256. BM=128 BN=128 BK=16, 256 thr,
// 8x8 microtile via FFMA2 (32 packed FMA per k).
// ---------------------------------------------------------------------------
__global__ void __launch_bounds__(256, 2)
k_xw(const float* __restrict__ Wk, const float* __restrict__ bias, int layer) {
    const int d = blockIdx.z;
    const int widx = d * 2 + layer;
    const float* __restrict__ x = (layer == 0) ? g_emb : g_y0[d];
    const float* __restrict__ W = Wk + (size_t)widx * En * Gn;
    const float* __restrict__ bi = bias + (size_t)widx * Gn;
    float* __restrict__ out = g_xW[d];
    const int n0 = blockIdx.x * 128;
    const int m0 = blockIdx.y * 128;
    const bool rev = (d == 1);
    const int tid = threadIdx.x;
    const int tx = tid & 15;   // 8 n cols at tx*8
    const int ty = tid >> 4;   // 8 m rows at ty*8

    __shared__ __align__(16) unsigned long long As2[16][130]; // (a,a) pairs [k][m]
    __shared__ __align__(16) float Bs[16][128];               // [k][n]

    unsigned long long acc2[8][4];
#pragma unroll
    for (int i = 0; i < 8; ++i)
#pragma unroll
        for (int j = 0; j < 4; ++j) acc2[i][j] = 0ull;

    // A loader: row ml, 8 k at kl
    const int ml = tid >> 1;
    const int kl = (tid & 1) * 8;
    const int m = m0 + ml;
    const int sA = m >> 3, bA = m & 7;
    const int tA = rev ? (Tn - 1 - sA) : sA;
    const float* xrow = x + (size_t)(bA * Tn + tA) * En;

    // B loader: k row kb, 8 n at nb
    const int kb = tid >> 4;
    const int nb = (tid & 15) * 8;

    for (int k0 = 0; k0 < En; k0 += 16) {
        {
            float4 v0 = *(const float4*)(xrow + k0 + kl);
            float4 v1 = *(const float4*)(xrow + k0 + kl + 4);
            As2[kl + 0][ml] = pack2(v0.x, v0.x);
            As2[kl + 1][ml] = pack2(v0.y, v0.y);
            As2[kl + 2][ml] = pack2(v0.z, v0.z);
            As2[kl + 3][ml] = pack2(v0.w, v0.w);
            As2[kl + 4][ml] = pack2(v1.x, v1.x);
            As2[kl + 5][ml] = pack2(v1.y, v1.y);
            As2[kl + 6][ml] = pack2(v1.z, v1.z);
            As2[kl + 7][ml] = pack2(v1.w, v1.w);
            const float* wr = W + (size_t)(k0 + kb) * Gn + n0 + nb;
            *(float4*)(&Bs[kb][nb]) = *(const float4*)(wr);
            *(float4*)(&Bs[kb][nb + 4]) = *(const float4*)(wr + 4);
        }
        __syncthreads();
#pragma unroll
        for (int k = 0; k < 16; ++k) {
            ulonglong2 a01 = *(const ulonglong2*)&As2[k][ty * 8];
            ulonglong2 a23 = *(const ulonglong2*)&As2[k][ty * 8 + 2];
            ulonglong2 a45 = *(const ulonglong2*)&As2[k][ty * 8 + 4];
            ulonglong2 a67 = *(const ulonglong2*)&As2[k][ty * 8 + 6];
            ulonglong2 bp0 = *(const ulonglong2*)&Bs[k][tx * 8];
            ulonglong2 bp1 = *(const ulonglong2*)&Bs[k][tx * 8 + 4];
            unsigned long long aa[8] = {a01.x, a01.y, a23.x, a23.y,
                                        a45.x, a45.y, a67.x, a67.y};
            unsigned long long bb[4] = {bp0.x, bp0.y, bp1.x, bp1.y};
#pragma unroll
            for (int i = 0; i < 8; ++i)
#pragma unroll
                for (int j = 0; j < 4; ++j) ffma2(acc2[i][j], aa[i], bb[j]);
        }
        __syncthreads();
    }
    float4 bva = *(const float4*)(bi + n0 + tx * 8);
    float4 bvb = *(const float4*)(bi + n0 + tx * 8 + 4);
#pragma unroll
    for (int i = 0; i < 8; ++i) {
        int mm = m0 + ty * 8 + i;
        float* op = out + (size_t)mm * Gn + n0 + tx * 8;
        float2 p0 = unpack2(acc2[i][0]);
        float2 p1 = unpack2(acc2[i][1]);
        float2 p2 = unpack2(acc2[i][2]);
        float2 p3 = unpack2(acc2[i][3]);
        *(float4*)(op) = make_float4(p0.x + bva.x, p0.y + bva.y,
                                     p1.x + bva.z, p1.y + bva.w);
        *(float4*)(op + 4) = make_float4(p2.x + bvb.x, p2.y + bvb.y,
                                         p3.x + bvb.z, p3.y + bvb.w);
    }
}

// ---------------------------------------------------------------------------
// Persistent LSTM recurrence. 128 blocks x 512 threads, 1 block/SM.
// Block bx: dir d = bx>>6, slice q = bx&63 -> units U0=q*32, proj cols P0=q*4.
// ---------------------------------------------------------------------------
__device__ __forceinline__ float fsig(float x) {
    return __fdividef(1.f, 1.f + __expf(-x));
}
__device__ __forceinline__ float ftanh(float x) {
    return __fdividef(2.f, 1.f + __expf(-2.f * x)) - 1.f;
}

// per-direction barrier: atomic arrive, thread-0 spins on one flag.
__device__ __forceinline__ void dir_barrier(int d, unsigned target, int tid) {
    __syncthreads();
    if (tid == 0) {
        __threadfence();
        unsigned old = atomicAdd(&g_cnt[d], 1u);
        if (old + 1u == target)
            *((volatile unsigned*)&g_flag[d]) = target;
        while ((int)(*((volatile unsigned*)&g_flag[d]) - target) < 0) {}
    }
    __syncthreads();
    __threadfence();
}

// SMEM float offsets
namespace {
constexpr int OF_WR = 0;       // [256][128]  (k*128+lc), lc = gate*32+u
constexpr int OF_WP = 32768;   // [2048][4]   interleaved (k*4+p)
constexpr int OF_HT = 40960;   // ull hT2[2048]: (h,h) at [p*8+b]   (4096 floats)
constexpr int OF_ZP = 45056;   // [8][8][128] (kc*1024 + b*128 + lc)
constexpr int OF_Z  = 53248;   // [8][128]
constexpr int OF_C  = 54272;   // [8][32]
constexpr int OF_RD = 54528;   // [8][2][4]
constexpr int SM_FLOATS = 54592;  // 218368 B
}

__global__ void __launch_bounds__(512, 1)
k_recur(const float* __restrict__ Wr, const float* __restrict__ Wp,
        const float* __restrict__ mask, int layer) {
    extern __shared__ __align__(16) float sm[];
    float* Wr_sm = sm + OF_WR;
    float* Wp_sm = sm + OF_WP;
    unsigned long long* hT2 = (unsigned long long*)(sm + OF_HT);
    float* zpart = sm + OF_ZP;
    float* z_sm  = sm + OF_Z;
    float* c_sm  = sm + OF_C;
    float* red   = sm + OF_RD;

    const int tid = threadIdx.x;
    const int bx = blockIdx.x;
    const int d = bx >> 6;
    const int q = bx & 63;
    const int U0 = q * 32;
    const int P0 = q * 4;
    const int widx = d * 2 + layer;

    // ---- preload weights ----
    {
        const float* Wg = Wr + (size_t)widx * Pn * Gn;
        for (int i = tid; i < 256 * 128; i += 512) {
            int k = i >> 7, lc = i & 127;
            int gate = lc >> 5, u = lc & 31;
            Wr_sm[i] = __ldg(&Wg[(size_t)k * Gn + gate * Hn + U0 + u]);
        }
        const float* Wpg = Wp + (size_t)widx * Hn * Pn;
        for (int k = tid; k < Hn; k += 512) {
            float4 v = __ldg((const float4*)&Wpg[(size_t)k * Pn + P0]);
            *(float4*)&Wp_sm[k * 4] = v;   // interleaved [k][4]
        }
    }
    if (tid < 256) c_sm[tid] = 0.f;

    const unsigned base = *((volatile unsigned*)&g_flag[d]);
    unsigned target = base;
    float h_own = 0.f;
    float* __restrict__ yb = (layer == 0) ? g_y0[d] : g_y1[d];
    float* __restrict__ hg = g_h[d];
    float* __restrict__ ag = g_a[d];
    const float* __restrict__ xWd = g_xW[d];
    __syncthreads();

    // role indices
    const int kc = tid >> 6;          // phase1: k-chunk (0..7, 32 k each)
    const int ch = (tid >> 5) & 1;    // phase1: column half (64 cols)
    const int cg = tid & 31;          // phase1: 2-col group
    const int rb = tid >> 6;          // reduce: batch
    const int l2 = (tid & 63) * 2;    // reduce: 2 cols
    const int rgate = l2 >> 5, ru = l2 & 31;
    const int w = tid >> 5;           // phase2 warp
    const int lane = tid & 31;
    const int pb = w >> 1;            // phase2 batch
    const int half = w & 1;           // phase2 k half

    for (int s = 0; s < Tn; ++s) {
        const int t = d ? (Tn - 1 - s) : s;

        // prefetch xW for the reduce stage (hide DRAM latency behind phase1)
        float2 xwv = __ldcg((const float2*)&xWd[((size_t)s * Bn + rb) * Gn +
                                                rgate * Hn + U0 + ru]);

        // ---- stage h packed (h,h): hT2[p*8+b] ----
        if (s == 0) {
            for (int i = tid; i < Bn * Pn; i += 512) hT2[(i & 255) * 8 + (i >> 8)] = 0ull;
        } else {
#pragma unroll
            for (int i = tid; i < Bn * Pn; i += 512) {
                float v = __ldcg(&hg[i]);
                hT2[(i & 255) * 8 + (i >> 8)] = pack2(v, v);
            }
        }
        __syncthreads();

        // ---- phase 1: z partials = h @ Wr  (all 512 threads, FFMA2) ----
        {
            unsigned long long acc2[8];
#pragma unroll
            for (int b = 0; b < 8; ++b) acc2[b] = 0ull;
            const float* wrbase = Wr_sm + ch * 64 + cg * 2;
            const int k0 = kc * 32;
#pragma unroll 4
            for (int k = k0; k < k0 + 32; ++k) {
                unsigned long long w2 = *(const unsigned long long*)(wrbase + k * 128);
                ulonglong2 h01 = *(const ulonglong2*)(hT2 + k * 8);
                ulonglong2 h23 = *(const ulonglong2*)(hT2 + k * 8 + 2);
                ulonglong2 h45 = *(const ulonglong2*)(hT2 + k * 8 + 4);
                ulonglong2 h67 = *(const ulonglong2*)(hT2 + k * 8 + 6);
                ffma2(acc2[0], h01.x, w2);
                ffma2(acc2[1], h01.y, w2);
                ffma2(acc2[2], h23.x, w2);
                ffma2(acc2[3], h23.y, w2);
                ffma2(acc2[4], h45.x, w2);
                ffma2(acc2[5], h45.y, w2);
                ffma2(acc2[6], h67.x, w2);
                ffma2(acc2[7], h67.y, w2);
            }
#pragma unroll
            for (int b = 0; b < 8; ++b)
                *(unsigned long long*)(zpart + kc * 1024 + b * 128 + ch * 64 + cg * 2) =
                    acc2[b];
        }
        __syncthreads();

        // ---- reduce k-chunks + add xW ----
        {
            float z0 = xwv.x, z1 = xwv.y;
#pragma unroll
            for (int kk = 0; kk < 8; ++kk) {
                float2 p = *(const float2*)(zpart + kk * 1024 + rb * 128 + l2);
                z0 += p.x;
                z1 += p.y;
            }
            *(float2*)(z_sm + rb * 128 + l2) = make_float2(z0, z1);
        }
        __syncthreads();

        // ---- gates / cell / a ----
        if (tid < 256) {
            const int b2 = tid >> 5, u = tid & 31;
            float zi = z_sm[b2 * 128 + u];
            float zf = z_sm[b2 * 128 + 32 + u];
            float zg = z_sm[b2 * 128 + 64 + u];
            float zo = z_sm[b2 * 128 + 96 + u];
            float ig = fsig(zi), fg = fsig(zf), gg = ftanh(zg), og = fsig(zo);
            float cold = c_sm[tid];
            float cn = fminf(3.f, fmaxf(-3.f, fg * cold + ig * gg));
            float mt = __ldg(&mask[b2 * Tn + t]);
            c_sm[tid] = (mt > 0.f) ? cn : cold;
            __stcg(&ag[b2 * Hn + U0 + u], og * ftanh(cn));
        }
        target += DBLK;
        dir_barrier(d, target, tid);

        // ---- phase 2: h cols P0..P0+3 = clip(a @ Wp)  (FFMA2, 2 packed acc) ----
        {
            const float4* av4 = (const float4*)(ag + pb * Hn + half * 1024);
            unsigned long long q01 = 0ull, q23 = 0ull;
#pragma unroll
            for (int j = 0; j < 8; ++j) {
                float4 av = __ldcg(av4 + lane + j * 32);
                const int kbase = half * 1024 + (lane + j * 32) * 4;
                {
                    ulonglong2 wv = *(const ulonglong2*)&Wp_sm[(kbase + 0) * 4];
                    unsigned long long ap = pack2(av.x, av.x);
                    ffma2(q01, ap, wv.x);
                    ffma2(q23, ap, wv.y);
                }
                {
                    ulonglong2 wv = *(const ulonglong2*)&Wp_sm[(kbase + 1) * 4];
                    unsigned long long ap = pack2(av.y, av.y);
                    ffma2(q01, ap, wv.x);
                    ffma2(q23, ap, wv.y);
                }
                {
                    ulonglong2 wv = *(const ulonglong2*)&Wp_sm[(kbase + 2) * 4];
                    unsigned long long ap = pack2(av.z, av.z);
                    ffma2(q01, ap, wv.x);
                    ffma2(q23, ap, wv.y);
                }
                {
                    ulonglong2 wv = *(const ulonglong2*)&Wp_sm[(kbase + 3) * 4];
                    unsigned long long ap = pack2(av.w, av.w);
                    ffma2(q01, ap, wv.x);
                    ffma2(q23, ap, wv.y);
                }
            }
            float2 f01 = unpack2(q01);
            float2 f23 = unpack2(q23);
            float q0 = f01.x, q1 = f01.y, q2 = f23.x, q3 = f23.y;
#pragma unroll
            for (int off = 16; off; off >>= 1) {
                q0 += __shfl_xor_sync(0xffffffffu, q0, off);
                q1 += __shfl_xor_sync(0xffffffffu, q1, off);
                q2 += __shfl_xor_sync(0xffffffffu, q2, off);
                q3 += __shfl_xor_sync(0xffffffffu, q3, off);
            }
            if (lane == 0)
                *(float4*)(red + (pb * 2 + half) * 4) = make_float4(q0, q1, q2, q3);
        }
        __syncthreads();
        if (tid < 32) {
            const int bb = tid >> 2, pp = tid & 3;
            float hv = red[(bb * 2) * 4 + pp] + red[(bb * 2 + 1) * 4 + pp];
            hv = fminf(3.f, fmaxf(-3.f, hv));
            float mt = __ldg(&mask[bb * Tn + t]);
            float hn = (mt > 0.f) ? hv : h_own;
            h_own = hn;
            __stcg(&hg[bb * Pn + P0 + pp], hn);
            yb[((size_t)bb * Tn + t) * Pn + P0 + pp] = hn;
        }
        target += DBLK;
        dir_barrier(d, target, tid);
    }
}

// ---------------------------------------------------------------------------
// Epilogue (unchanged)
// ---------------------------------------------------------------------------
__device__ __forceinline__ float layer_val(int l, int b, int t, int ch) {
    if (l == 0) return g_emb[(size_t)(b * Tn + t) * En + (ch & 255)];
    const int dd = ch >> 8;
    const size_t idx = (size_t)(b * Tn + t) * Pn + (ch & 255);
    float v = g_y0[dd][idx];
    if (l == 2) v += g_y1[dd][idx];
    return v;
}

__global__ void k_stats(const float* __restrict__ mask) {
    const int b = blockIdx.x;
    const int l = blockIdx.y;
    __shared__ float red[256];
    const int tid = threadIdx.x;

    float nm = 0.f;
    for (int t = tid; t < Tn; t += 256) nm += mask[b * Tn + t];
    red[tid] = nm;
    __syncthreads();
    for (int st = 128; st > 0; st >>= 1) {
        if (tid < st) red[tid] += red[tid + st];
        __syncthreads();
    }
    const float num = red[0];
    __syncthreads();

    float smv = 0.f;
    for (int i = tid; i < Tn * 512; i += 256) {
        int t = i >> 9, ch = i & 511;
        smv += layer_val(l, b, t, ch) * mask[b * Tn + t];
    }
    red[tid] = smv;
    __syncthreads();
    for (int st = 128; st > 0; st >>= 1) {
        if (tid < st) red[tid] += red[tid + st];
        __syncthreads();
    }
    const float mean = red[0] / num;
    __syncthreads();

    float vs = 0.f;
    for (int i = tid; i < Tn * 512; i += 256) {
        int t = i >> 9, ch = i & 511;
        float m = mask[b * Tn + t];
        float dd = (layer_val(l, b, t, ch) * m - mean) * m;
        vs += dd * dd;
    }
    red[tid] = vs;
    __syncthreads();
    for (int st = 128; st > 0; st >>= 1) {
        if (tid < st) red[tid] += red[tid + st];
        __syncthreads();
    }
    if (tid == 0) {
        g_mean[l][b] = mean;
        g_var[l][b] = red[0] / num;
    }
}

__global__ void k_final(const float* __restrict__ elmo_w, const float* __restrict__ gamma,
                        float* __restrict__ out) {
    const int i = blockIdx.x * 256 + threadIdx.x;
    const int ch = i & 511;
    const int bt = i >> 9;
    const int b = bt / Tn;
    const int t = bt - b * Tn;
    float w0 = elmo_w[0], w1 = elmo_w[1], w2 = elmo_w[2];
    float mx = fmaxf(w0, fmaxf(w1, w2));
    float e0 = expf(w0 - mx), e1 = expf(w1 - mx), e2 = expf(w2 - mx);
    float inv = 1.f / (e0 + e1 + e2);
    float gm = gamma[0];
    float r = 0.f;
    r += e0 * inv * (layer_val(0, b, t, ch) - g_mean[0][b]) / sqrtf(g_var[0][b] + 1e-12f);
    r += e1 * inv * (layer_val(1, b, t, ch) - g_mean[1][b]) / sqrtf(g_var[1][b] + 1e-12f);
    r += e2 * inv * (layer_val(2, b, t, ch) - g_mean[2][b]) / sqrtf(g_var[2][b] + 1e-12f);
    out[i] = gm * r;
}

// ---------------------------------------------------------------------------
extern "C" void kernel_launch(void* const* d_in, const int* in_sizes, int n_in,
                              void* d_out, int out_size) {
    (void)in_sizes; (void)n_in; (void)out_size;
    const int*   tokens = (const int*)d_in[0];
    const float* mask   = (const float*)d_in[1];
    const float* table  = (const float*)d_in[2];
    const float* Wk     = (const float*)d_in[3];
    const float* Wr     = (const float*)d_in[4];
    const float* bias   = (const float*)d_in[5];
    const float* Wp     = (const float*)d_in[6];
    const float* elmo_w = (const float*)d_in[7];
    const float* gamma  = (const float*)d_in[8];
    float* out = (float*)d_out;

    const int recur_smem = SM_FLOATS * 4;  // 218368 B
    cudaFuncSetAttribute(k_recur, cudaFuncAttributeMaxDynamicSharedMemorySize,
                         recur_smem);

    k_embed<<<768, 256>>>(tokens, table);
    for (int layer = 0; layer < 2; ++layer) {
        k_xw<<<dim3(Gn / 128, (Tn * Bn) / 128, 2), 256>>>(Wk, bias, layer);
        k_recur<<<NBLK, 512, recur_smem>>>(Wr, Wp, mask, layer);
    }
    k_stats<<<dim3(8, 3), 256>>>(mask);
    k_final<<<1536, 256>>>(elmo_w, gamma, out);
}

// round 11
// speedup vs baseline: 1.2562x; 1.2562x over previous
#include <cuda_runtime.h>
#include <cuda_bf16.h>
#include <mma.h>
#include <math.h>

using namespace nvcuda;

// ---------------------------------------------------------------------------
// ELMo embeddings. xW GEMM on tensor cores (3xTF32); persistent fp32 LSTM
// recurrence (R9 mapping) with per-direction grid barrier.
// ---------------------------------------------------------------------------

namespace {
constexpr int Bn = 8;     // batch
constexpr int Tn = 96;    // time
constexpr int En = 256;   // embed dim
constexpr int Hn = 2048;  // hidden
constexpr int Pn = 256;   // projection
constexpr int Gn = 8192;  // 4*H
constexpr int NBLK = 128; // persistent grid (2 dirs x 64)
constexpr int DBLK = 64;  // blocks per direction
}

// scratch (device globals; allocation-free)
__device__ float g_emb[Bn * Tn * En];
__device__ float g_y0[2][Bn * Tn * Pn];
__device__ float g_y1[2][Bn * Tn * Pn];
__device__ float g_xW[2][(size_t)Tn * Bn * Gn];  // x@Wk+b, step-major
__device__ float g_h[2][Bn * Pn];
__device__ float g_a[2][Bn * Hn];
__device__ float g_mean[3][Bn];
__device__ float g_var[3][Bn];

// per-direction barrier state (monotonic; never reset -> graph-replay safe)
__device__ unsigned g_cnt[2];
__device__ unsigned g_flag[2];

// ---------------------------------------------------------------------------
__global__ void k_embed(const int* __restrict__ tok, const float* __restrict__ tab) {
    int i = blockIdx.x * 256 + threadIdx.x;  // B*T*E = 196608
    int bt = i >> 8;
    int e = i & 255;
    g_emb[i] = tab[(size_t)tok[bt] * En + e];
}

// ---- tf32 split helpers ----------------------------------------------------
__device__ __forceinline__ float to_tf32(float v) {
    float r;
    asm("cvt.rna.tf32.f32 %0, %1;" : "=f"(r) : "f"(v));
    return r;
}

// ---------------------------------------------------------------------------
// xW GEMM on tensor cores, 3xTF32 split for fp32-grade accuracy.
// M=768 (s,b), N=8192, K=256. Block tile 64x128, 8 warps (2x4), each warp
// 32x32 via 2x2 wmma m16n16k8 fragments. BK=32 staged hi/lo in SMEM.
// ---------------------------------------------------------------------------
namespace {
constexpr int XA_LD = 40;    // As leading dim (floats)
constexpr int XB_LD = 136;   // Bs leading dim (floats)
constexpr int XOF_AHI = 0;                  // [64][40]
constexpr int XOF_ALO = 64 * XA_LD;         // 2560
constexpr int XOF_BHI = 2 * 64 * XA_LD;     // 5120, [32][136]
constexpr int XOF_BLO = XOF_BHI + 32 * XB_LD;
constexpr int X_SMEM_FLOATS = XOF_BLO + 32 * XB_LD;  // 13824 floats = 55296 B
constexpr int XO_LD = 132;   // output staging leading dim (reuses same SMEM)
}

__global__ void __launch_bounds__(256, 2)
k_xw(const float* __restrict__ Wk, const float* __restrict__ bias, int layer) {
    const int d = blockIdx.z;
    const int widx = d * 2 + layer;
    const float* __restrict__ x = (layer == 0) ? g_emb : g_y0[d];
    const float* __restrict__ W = Wk + (size_t)widx * En * Gn;
    const float* __restrict__ bi = bias + (size_t)widx * Gn;
    float* __restrict__ out = g_xW[d];
    const int n0 = blockIdx.x * 128;
    const int m0 = blockIdx.y * 64;
    const bool rev = (d == 1);
    const int tid = threadIdx.x;

    extern __shared__ __align__(16) float xsm[];
    float* As_hi = xsm + XOF_AHI;
    float* As_lo = xsm + XOF_ALO;
    float* Bs_hi = xsm + XOF_BHI;
    float* Bs_lo = xsm + XOF_BLO;

    const int wid = tid >> 5;
    const int wr = wid >> 2;       // warp row (2 x 32 rows)
    const int wc = wid & 3;        // warp col (4 x 32 cols)

    wmma::fragment<wmma::accumulator, 16, 16, 8, float> acc[2][2];
#pragma unroll
    for (int i = 0; i < 2; ++i)
#pragma unroll
        for (int j = 0; j < 2; ++j) wmma::fill_fragment(acc[i][j], 0.f);

    // A loader: row ml (0..63), 8 k at kl
    const int ml = tid >> 2;
    const int kl = (tid & 3) * 8;
    const int m = m0 + ml;
    const int sA = m >> 3, bA = m & 7;
    const int tA = rev ? (Tn - 1 - sA) : sA;
    const float* xrow = x + (size_t)(bA * Tn + tA) * En;

    // B loader: k row kb (0..31), 16 n at nb
    const int kb = tid >> 3;
    const int nb = (tid & 7) * 16;

    for (int k0 = 0; k0 < En; k0 += 32) {
        {
            float4 v0 = *(const float4*)(xrow + k0 + kl);
            float4 v1 = *(const float4*)(xrow + k0 + kl + 4);
            float va[8] = {v0.x, v0.y, v0.z, v0.w, v1.x, v1.y, v1.z, v1.w};
#pragma unroll
            for (int j = 0; j < 8; ++j) {
                float hi = to_tf32(va[j]);
                As_hi[ml * XA_LD + kl + j] = hi;
                As_lo[ml * XA_LD + kl + j] = to_tf32(va[j] - hi);
            }
            const float* wrg = W + (size_t)(k0 + kb) * Gn + n0 + nb;
#pragma unroll
            for (int j4 = 0; j4 < 16; j4 += 4) {
                float4 wv = *(const float4*)(wrg + j4);
                float wb[4] = {wv.x, wv.y, wv.z, wv.w};
#pragma unroll
                for (int j = 0; j < 4; ++j) {
                    float hi = to_tf32(wb[j]);
                    Bs_hi[kb * XB_LD + nb + j4 + j] = hi;
                    Bs_lo[kb * XB_LD + nb + j4 + j] = to_tf32(wb[j] - hi);
                }
            }
        }
        __syncthreads();
#pragma unroll
        for (int kk = 0; kk < 32; kk += 8) {
            wmma::fragment<wmma::matrix_a, 16, 16, 8, wmma::precision::tf32,
                           wmma::row_major> ahi[2], alo[2];
            wmma::fragment<wmma::matrix_b, 16, 16, 8, wmma::precision::tf32,
                           wmma::row_major> bhi[2], blo[2];
#pragma unroll
            for (int i = 0; i < 2; ++i) {
                wmma::load_matrix_sync(ahi[i],
                    As_hi + (wr * 32 + i * 16) * XA_LD + kk, XA_LD);
                wmma::load_matrix_sync(alo[i],
                    As_lo + (wr * 32 + i * 16) * XA_LD + kk, XA_LD);
                wmma::load_matrix_sync(bhi[i],
                    Bs_hi + kk * XB_LD + wc * 32 + i * 16, XB_LD);
                wmma::load_matrix_sync(blo[i],
                    Bs_lo + kk * XB_LD + wc * 32 + i * 16, XB_LD);
            }
#pragma unroll
            for (int i = 0; i < 2; ++i)
#pragma unroll
                for (int j = 0; j < 2; ++j) {
                    wmma::mma_sync(acc[i][j], alo[i], bhi[j], acc[i][j]);
                    wmma::mma_sync(acc[i][j], ahi[i], blo[j], acc[i][j]);
                    wmma::mma_sync(acc[i][j], ahi[i], bhi[j], acc[i][j]);
                }
        }
        __syncthreads();
    }

    // stage results in SMEM, add bias, write coalesced
    float* outs = xsm;  // [64][132]
#pragma unroll
    for (int i = 0; i < 2; ++i)
#pragma unroll
        for (int j = 0; j < 2; ++j)
            wmma::store_matrix_sync(
                outs + (wr * 32 + i * 16) * XO_LD + wc * 32 + j * 16,
                acc[i][j], XO_LD, wmma::mem_row_major);
    __syncthreads();
    {
        const int r = tid >> 2;            // 0..63
        const int c0 = (tid & 3) * 32;     // 32 consecutive n
        const int mm = m0 + r;
        float* op = out + (size_t)mm * Gn + n0 + c0;
        const float* ip = outs + r * XO_LD + c0;
        const float* bp = bi + n0 + c0;
#pragma unroll
        for (int j4 = 0; j4 < 32; j4 += 4) {
            float4 v = *(const float4*)(ip + j4);
            float4 bv = *(const float4*)(bp + j4);
            *(float4*)(op + j4) = make_float4(v.x + bv.x, v.y + bv.y,
                                              v.z + bv.z, v.w + bv.w);
        }
    }
}

// ---------------------------------------------------------------------------
// Persistent LSTM recurrence (R9 version). 128 blocks x 512 threads.
// Block bx: dir d = bx>>6, slice q = bx&63 -> units U0=q*32, proj cols P0=q*4.
// ---------------------------------------------------------------------------
__device__ __forceinline__ float fsig(float x) {
    return __fdividef(1.f, 1.f + __expf(-x));
}
__device__ __forceinline__ float ftanh(float x) {
    return __fdividef(2.f, 1.f + __expf(-2.f * x)) - 1.f;
}

__device__ __forceinline__ void dir_barrier(int d, unsigned target, int tid) {
    __syncthreads();
    if (tid == 0) {
        __threadfence();
        unsigned old = atomicAdd(&g_cnt[d], 1u);
        if (old + 1u == target)
            *((volatile unsigned*)&g_flag[d]) = target;
        while ((int)(*((volatile unsigned*)&g_flag[d]) - target) < 0) {}
    }
    __syncthreads();
    __threadfence();
}

__global__ void __launch_bounds__(512, 1)
k_recur(const float* __restrict__ Wr, const float* __restrict__ Wp,
        const float* __restrict__ mask, int layer) {
    extern __shared__ float sm[];
    float* Wr_sm = sm;            // [256][128] (k*128+lc), lc = gate*32+u
    float* Wp_sm = sm + 32768;    // [4][2048]  (p*2048+k)
    float* hT    = sm + 40960;    // [256][8]   (p*8+b)  transposed h
    float* zpart = sm + 43008;    // [8][8][128] (kc*1024 + b*128 + lc)
    float* z_sm  = sm + 51200;    // [8][128]
    float* c_sm  = sm + 52224;    // [8][32]
    float* red   = sm + 52480;    // [8][2][4]
    // total 52544 floats = 210176 B

    const int tid = threadIdx.x;
    const int bx = blockIdx.x;
    const int d = bx >> 6;
    const int q = bx & 63;
    const int U0 = q * 32;
    const int P0 = q * 4;
    const int widx = d * 2 + layer;

    // ---- preload weights ----
    {
        const float* Wg = Wr + (size_t)widx * Pn * Gn;
        for (int i = tid; i < 256 * 128; i += 512) {
            int k = i >> 7, lc = i & 127;
            int gate = lc >> 5, u = lc & 31;
            Wr_sm[i] = __ldg(&Wg[(size_t)k * Gn + gate * Hn + U0 + u]);
        }
        const float* Wpg = Wp + (size_t)widx * Hn * Pn;
        for (int k = tid; k < Hn; k += 512) {
            float4 v = __ldg((const float4*)&Wpg[(size_t)k * Pn + P0]);
            Wp_sm[k] = v.x;
            Wp_sm[2048 + k] = v.y;
            Wp_sm[4096 + k] = v.z;
            Wp_sm[6144 + k] = v.w;
        }
    }
    if (tid < 256) c_sm[tid] = 0.f;

    const unsigned base = *((volatile unsigned*)&g_flag[d]);
    unsigned target = base;
    float h_own = 0.f;
    float* __restrict__ yb = (layer == 0) ? g_y0[d] : g_y1[d];
    float* __restrict__ hg = g_h[d];
    float* __restrict__ ag = g_a[d];
    const float* __restrict__ xWd = g_xW[d];
    __syncthreads();

    // role indices
    const int kc = tid >> 5;          // phase1 (tid<256): k-chunk
    const int cg = tid & 31;          // phase1: 4-col group
    const int rb = tid >> 6;          // reduce: batch
    const int l2 = (tid & 63) * 2;    // reduce: 2 cols
    const int rgate = l2 >> 5, ru = l2 & 31;
    const int w = tid >> 5;           // phase2 warp
    const int lane = tid & 31;
    const int pb = w >> 1;            // phase2 batch
    const int half = w & 1;           // phase2 k half

    for (int s = 0; s < Tn; ++s) {
        const int t = d ? (Tn - 1 - s) : s;

        // prefetch xW for the reduce stage (hide DRAM latency behind phase1)
        float2 xwv = __ldcg((const float2*)&xWd[((size_t)s * Bn + rb) * Gn +
                                                rgate * Hn + U0 + ru]);

        // ---- stage h transposed: hT[p*8+b] = h[b*256+p] ----
        if (s == 0) {
            for (int i = tid; i < Bn * Pn; i += 512) hT[i] = 0.f;
        } else {
#pragma unroll
            for (int i = tid; i < Bn * Pn; i += 512) {
                int b = i >> 8, p = i & 255;
                hT[p * 8 + b] = __ldcg(&hg[i]);
            }
        }
        __syncthreads();

        // ---- phase 1: z partials = h @ Wr (8 k-chunks of 32) ----
        if (tid < 256) {
            float acc[8][4];
#pragma unroll
            for (int b = 0; b < 8; ++b)
                acc[b][0] = acc[b][1] = acc[b][2] = acc[b][3] = 0.f;
            const float* wr0 = Wr_sm + cg * 4;
            const int ke = kc * 32 + 32;
#pragma unroll 4
            for (int k = kc * 32; k < ke; ++k) {
                float4 wv = *(const float4*)(wr0 + k * 128);
                float h8[8];
                *(float4*)(h8) = *(const float4*)(hT + k * 8);
                *(float4*)(h8 + 4) = *(const float4*)(hT + k * 8 + 4);
#pragma unroll
                for (int b = 0; b < 8; ++b) {
                    acc[b][0] += wv.x * h8[b];
                    acc[b][1] += wv.y * h8[b];
                    acc[b][2] += wv.z * h8[b];
                    acc[b][3] += wv.w * h8[b];
                }
            }
#pragma unroll
            for (int b = 0; b < 8; ++b)
                *(float4*)(zpart + kc * 1024 + b * 128 + cg * 4) =
                    make_float4(acc[b][0], acc[b][1], acc[b][2], acc[b][3]);
        }
        __syncthreads();

        // ---- reduce k-chunks + add xW ----
        {
            float z0 = xwv.x, z1 = xwv.y;
#pragma unroll
            for (int kk = 0; kk < 8; ++kk) {
                float2 p = *(const float2*)(zpart + kk * 1024 + rb * 128 + l2);
                z0 += p.x;
                z1 += p.y;
            }
            *(float2*)(z_sm + rb * 128 + l2) = make_float2(z0, z1);
        }
        __syncthreads();

        // ---- gates / cell / a ----
        if (tid < 256) {
            const int b2 = tid >> 5, u = tid & 31;
            float zi = z_sm[b2 * 128 + u];
            float zf = z_sm[b2 * 128 + 32 + u];
            float zg = z_sm[b2 * 128 + 64 + u];
            float zo = z_sm[b2 * 128 + 96 + u];
            float ig = fsig(zi), fg = fsig(zf), gg = ftanh(zg), og = fsig(zo);
            float cold = c_sm[tid];
            float cn = fminf(3.f, fmaxf(-3.f, fg * cold + ig * gg));
            float mt = __ldg(&mask[b2 * Tn + t]);
            c_sm[tid] = (mt > 0.f) ? cn : cold;
            __stcg(&ag[b2 * Hn + U0 + u], og * ftanh(cn));
        }
        target += DBLK;
        dir_barrier(d, target, tid);

        // ---- phase 2: h cols P0..P0+3 = clip(a @ Wp) ----
        {
            const float4* av4 = (const float4*)(ag + pb * Hn + half * 1024);
            float q0 = 0.f, q1 = 0.f, q2 = 0.f, q3 = 0.f;
#pragma unroll
            for (int j = 0; j < 8; ++j) {
                float4 av = __ldcg(av4 + lane + j * 32);
                const int kk = half * 1024 + (lane + j * 32) * 4;
                float4 wa = *(const float4*)&Wp_sm[kk];
                float4 wb = *(const float4*)&Wp_sm[2048 + kk];
                float4 wc = *(const float4*)&Wp_sm[4096 + kk];
                float4 wd = *(const float4*)&Wp_sm[6144 + kk];
                q0 += av.x * wa.x + av.y * wa.y + av.z * wa.z + av.w * wa.w;
                q1 += av.x * wb.x + av.y * wb.y + av.z * wb.z + av.w * wb.w;
                q2 += av.x * wc.x + av.y * wc.y + av.z * wc.z + av.w * wc.w;
                q3 += av.x * wd.x + av.y * wd.y + av.z * wd.z + av.w * wd.w;
            }
#pragma unroll
            for (int off = 16; off; off >>= 1) {
                q0 += __shfl_xor_sync(0xffffffffu, q0, off);
                q1 += __shfl_xor_sync(0xffffffffu, q1, off);
                q2 += __shfl_xor_sync(0xffffffffu, q2, off);
                q3 += __shfl_xor_sync(0xffffffffu, q3, off);
            }
            if (lane == 0)
                *(float4*)(red + (pb * 2 + half) * 4) = make_float4(q0, q1, q2, q3);
        }
        __syncthreads();
        if (tid < 32) {
            const int bb = tid >> 2, pp = tid & 3;
            float hv = red[(bb * 2) * 4 + pp] + red[(bb * 2 + 1) * 4 + pp];
            hv = fminf(3.f, fmaxf(-3.f, hv));
            float mt = __ldg(&mask[bb * Tn + t]);
            float hn = (mt > 0.f) ? hv : h_own;
            h_own = hn;
            __stcg(&hg[bb * Pn + P0 + pp], hn);
            yb[((size_t)bb * Tn + t) * Pn + P0 + pp] = hn;
        }
        target += DBLK;
        dir_barrier(d, target, tid);
    }
}

// ---------------------------------------------------------------------------
// Epilogue (unchanged)
// ---------------------------------------------------------------------------
__device__ __forceinline__ float layer_val(int l, int b, int t, int ch) {
    if (l == 0) return g_emb[(size_t)(b * Tn + t) * En + (ch & 255)];
    const int dd = ch >> 8;
    const size_t idx = (size_t)(b * Tn + t) * Pn + (ch & 255);
    float v = g_y0[dd][idx];
    if (l == 2) v += g_y1[dd][idx];
    return v;
}

__global__ void k_stats(const float* __restrict__ mask) {
    const int b = blockIdx.x;
    const int l = blockIdx.y;
    __shared__ float red[256];
    const int tid = threadIdx.x;

    float nm = 0.f;
    for (int t = tid; t < Tn; t += 256) nm += mask[b * Tn + t];
    red[tid] = nm;
    __syncthreads();
    for (int st = 128; st > 0; st >>= 1) {
        if (tid < st) red[tid] += red[tid + st];
        __syncthreads();
    }
    const float num = red[0];
    __syncthreads();

    float smv = 0.f;
    for (int i = tid; i < Tn * 512; i += 256) {
        int t = i >> 9, ch = i & 511;
        smv += layer_val(l, b, t, ch) * mask[b * Tn + t];
    }
    red[tid] = smv;
    __syncthreads();
    for (int st = 128; st > 0; st >>= 1) {
        if (tid < st) red[tid] += red[tid + st];
        __syncthreads();
    }
    const float mean = red[0] / num;
    __syncthreads();

    float vs = 0.f;
    for (int i = tid; i < Tn * 512; i += 256) {
        int t = i >> 9, ch = i & 511;
        float m = mask[b * Tn + t];
        float dd = (layer_val(l, b, t, ch) * m - mean) * m;
        vs += dd * dd;
    }
    red[tid] = vs;
    __syncthreads();
    for (int st = 128; st > 0; st >>= 1) {
        if (tid < st) red[tid] += red[tid + st];
        __syncthreads();
    }
    if (tid == 0) {
        g_mean[l][b] = mean;
        g_var[l][b] = red[0] / num;
    }
}

__global__ void k_final(const float* __restrict__ elmo_w, const float* __restrict__ gamma,
                        float* __restrict__ out) {
    const int i = blockIdx.x * 256 + threadIdx.x;
    const int ch = i & 511;
    const int bt = i >> 9;
    const int b = bt / Tn;
    const int t = bt - b * Tn;
    float w0 = elmo_w[0], w1 = elmo_w[1], w2 = elmo_w[2];
    float mx = fmaxf(w0, fmaxf(w1, w2));
    float e0 = expf(w0 - mx), e1 = expf(w1 - mx), e2 = expf(w2 - mx);
    float inv = 1.f / (e0 + e1 + e2);
    float gm = gamma[0];
    float r = 0.f;
    r += e0 * inv * (layer_val(0, b, t, ch) - g_mean[0][b]) / sqrtf(g_var[0][b] + 1e-12f);
    r += e1 * inv * (layer_val(1, b, t, ch) - g_mean[1][b]) / sqrtf(g_var[1][b] + 1e-12f);
    r += e2 * inv * (layer_val(2, b, t, ch) - g_mean[2][b]) / sqrtf(g_var[2][b] + 1e-12f);
    out[i] = gm * r;
}

// ---------------------------------------------------------------------------
extern "C" void kernel_launch(void* const* d_in, const int* in_sizes, int n_in,
                              void* d_out, int out_size) {
    (void)in_sizes; (void)n_in; (void)out_size;
    const int*   tokens = (const int*)d_in[0];
    const float* mask   = (const float*)d_in[1];
    const float* table  = (const float*)d_in[2];
    const float* Wk     = (const float*)d_in[3];
    const float* Wr     = (const float*)d_in[4];
    const float* bias   = (const float*)d_in[5];
    const float* Wp     = (const float*)d_in[6];
    const float* elmo_w = (const float*)d_in[7];
    const float* gamma  = (const float*)d_in[8];
    float* out = (float*)d_out;

    const int recur_smem = 210176;              // 52544 floats
    const int xw_smem = X_SMEM_FLOATS * 4;      // 55296 B
    cudaFuncSetAttribute(k_recur, cudaFuncAttributeMaxDynamicSharedMemorySize,
                         recur_smem);
    cudaFuncSetAttribute(k_xw, cudaFuncAttributeMaxDynamicSharedMemorySize,
                         xw_smem);

    k_embed<<<768, 256>>>(tokens, table);
    for (int layer = 0; layer < 2; ++layer) {
        k_xw<<<dim3(Gn / 128, (Tn * Bn) / 64, 2), 256, xw_smem>>>(Wk, bias, layer);
        k_recur<<<NBLK, 512, recur_smem>>>(Wr, Wp, mask, layer);
    }
    k_stats<<<dim3(8, 3), 256>>>(mask);
    k_final<<<1536, 256>>>(elmo_w, gamma, out);
}